// round 11
// baseline (speedup 1.0000x reference)
#include <cuda_runtime.h>
#include <stdint.h>
#include <math.h>

#define BB 256      // batch
#define TT 512      // time
#define NPOS 128
#define NACT 32
#define DIN 160     // NPOS + NACT
#define HH 512      // hidden
#define G4 2048     // 4*H
#define KTOT 672    // HH + DIN
#define NCHUNK 21   // KTOT / 32
// stage: W-dup 32x128 floats + src 32x68 floats
#define WSTG 4096
#define STAGE_F (WSTG + 2176)                 // 6272 floats
#define SMEM_BYTES (4 * STAGE_F * 4)          // 100352 B dynamic smem

// ---- persistent scratch (device globals) ----
__device__ __align__(16) float g_WT2[KTOT * 2 * G4];  // WT dup: [k][2g],[2g+1] = WT[k][g] (11 MB)
__device__ __align__(16) float g_xT[TT * DIN * BB];   // xT[t][d][b]
__device__ __align__(16) float g_h[2][HH * BB];       // h[j][b] ping-pong
__device__ __align__(16) float g_c[HH * BB];          // c[j][b]
__device__ __align__(16) float g_bias[G4];            // b_ih + b_hh

// ------------------------------------------------------------------ init ----
__global__ void k_bias(const float* __restrict__ b_ih, const float* __restrict__ b_hh) {
    int i = blockIdx.x * blockDim.x + threadIdx.x;
    if (i < G4) g_bias[i] = b_ih[i] + b_hh[i];
}

__global__ void k_out_init(float* __restrict__ out, const float* __restrict__ b_out) {
    int i = blockIdx.x * blockDim.x + threadIdx.x;
    if (i < BB * TT) out[i] = b_out[0];
}

__global__ void k_wt(const float* __restrict__ W_hh, const float* __restrict__ W_ih) {
    int idx = blockIdx.x * blockDim.x + threadIdx.x;
    if (idx >= KTOT * G4) return;
    int k = idx / G4;
    int g = idx - k * G4;
    float v = (k < HH) ? W_hh[g * HH + k] : W_ih[g * DIN + (k - HH)];
    g_WT2[(long)k * (2 * G4) + 2 * g]     = v;
    g_WT2[(long)k * (2 * G4) + 2 * g + 1] = v;
}

// tiled transpose of concat(obs, act): x[b][t][d] -> xT[t][d][b]
__global__ void k_xt(const float* __restrict__ obs, const float* __restrict__ act) {
    __shared__ float tile[32][33];
    int t  = blockIdx.x;
    int d0 = blockIdx.y * 32;
    int b0 = blockIdx.z * 32;
    int tx = threadIdx.x;
    int ty = threadIdx.y;
#pragma unroll
    for (int i = 0; i < 4; ++i) {
        int bl = ty + i * 8;
        int b = b0 + bl;
        int d = d0 + tx;
        float v;
        if (d < NPOS) v = obs[((long)b * TT + t) * NPOS + d];
        else          v = act[((long)b * TT + t) * NACT + (d - NPOS)];
        tile[bl][tx] = v;
    }
    __syncthreads();
#pragma unroll
    for (int i = 0; i < 4; ++i) {
        int dl = ty + i * 8;
        int d = d0 + dl;
        int b = b0 + tx;
        g_xT[((long)t * DIN + d) * BB + b] = tile[tx][dl];
    }
}

__global__ void k_state(const float* __restrict__ h0, const float* __restrict__ c0) {
    int idx = blockIdx.x * blockDim.x + threadIdx.x;
    if (idx >= HH * BB) return;
    int j = idx >> 8;
    int b = idx & 255;
    g_h[0][idx] = h0[b * HH + j];
    g_c[idx]    = c0[b * HH + j];
}

// ------------------------------------------------------------- utilities ----
__device__ __forceinline__ void cp16(uint32_t saddr, const float* g) {
    asm volatile("cp.async.cg.shared.global [%0], [%1], 16;"
                 :: "r"(saddr), "l"(g) : "memory");
}
__device__ __forceinline__ void cp_commit() {
    asm volatile("cp.async.commit_group;" ::: "memory");
}
__device__ __forceinline__ void cp_wait2() {
    asm volatile("cp.async.wait_group 2;" ::: "memory");
}

__device__ __forceinline__ void fma2(unsigned long long& d,
                                     unsigned long long a,
                                     unsigned long long b) {
    asm("fma.rn.f32x2 %0, %1, %2, %0;" : "+l"(d) : "l"(a), "l"(b));
}
__device__ __forceinline__ void unpack2(unsigned long long v, float& lo, float& hi) {
    asm("mov.b64 {%0, %1}, %2;" : "=f"(lo), "=f"(hi) : "l"(v));
}

__device__ __forceinline__ float fsig(float x) {
    return 1.0f / (1.0f + __expf(-x));
}
__device__ __forceinline__ float ftanh(float x) {
    return 1.0f - 2.0f / (__expf(2.0f * x) + 1.0f);
}

// ------------------------------------------------------------------ step ----
// grid (32 j-tiles, 4 b-tiles), 256 threads.
// CTA: 64 gate rows (16 j x 4 quadrants) x 64 batch. M=64,N=64,K=672.
// 4-stage cp.async pipeline; inner product via packed fma.rn.f32x2.
__global__ void __launch_bounds__(256, 1)
step_kernel(int t, int par,
            const float* __restrict__ W_out,
            float* __restrict__ out) {
    extern __shared__ float sm[];

    const int j0 = blockIdx.x * 16;
    const int b0 = blockIdx.y * 64;
    const int tid = threadIdx.x;
    const int tx = tid & 15;        // n direction (4 cols each)
    const int ty = tid >> 4;        // m direction (4 gate cols each)

    const float* __restrict__ hin = g_h[par];
    float* __restrict__ hout = g_h[par ^ 1];

    uint32_t sbase;
    asm("{ .reg .u64 tt; cvta.to.shared.u64 tt, %1; cvt.u32.u64 %0, tt; }"
        : "=r"(sbase) : "l"(sm));

    // ---- cp.async slot precompute ----
    // W (dup): 1024 cp16 per chunk. tid -> kkw = tid>>3 (0..31), s = tid&7;
    // 4 slots s8 = s + 8*i cover gate-col pairs (2*s8, 2*s8+1).
    const int kkw = tid >> 3;
    const int sW  = tid & 7;
    // per-slot W gmem float offsets (within chunk) and smem byte offsets
    int wgo[4];
    uint32_t wso[4];
#pragma unroll
    for (int i = 0; i < 4; ++i) {
        int s8 = sW + 8 * i;                       // 0..31
        int quad = s8 >> 3;                        // (2*s8)>>4
        wgo[i] = kkw * (2 * G4) + 2 * (quad * 512 + j0) + 4 * (s8 & 7);
        wso[i] = (uint32_t)(kkw * 128 + s8 * 4) * 4;
    }
    // B: 512 cp16 per chunk. kk0 = tid>>4 (0..15), m4 = tid&15; slots kk0, kk0+16.
    const int kk0 = tid >> 4;
    const int m4  = tid & 15;
    const uint32_t ssB0 = (uint32_t)(WSTG + kk0 * 68 + m4 * 4) * 4;
    const uint32_t ssB1 = (uint32_t)(WSTG + (kk0 + 16) * 68 + m4 * 4) * 4;

    unsigned long long acc2[4][2];
#pragma unroll
    for (int i = 0; i < 4; ++i) { acc2[i][0] = 0ULL; acc2[i][1] = 0ULL; }

    // issue chunk c into stage c&3
    auto issue = [&](int c) {
        const float* __restrict__ wsrc = g_WT2 + (long)c * 32 * (2 * G4);
        const float* __restrict__ bs = (c < 16)
            ? (hin + (long)c * 32 * BB + b0)
            : (g_xT + ((long)t * DIN + (c * 32 - HH)) * BB + b0);
        uint32_t st = sbase + (uint32_t)(c & 3) * (STAGE_F * 4);
#pragma unroll
        for (int i = 0; i < 4; ++i) cp16(st + wso[i], wsrc + wgo[i]);
        cp16(st + ssB0, bs + kk0 * BB + m4 * 4);
        cp16(st + ssB1, bs + (kk0 + 16) * BB + m4 * 4);
    };

    issue(0); cp_commit();
    issue(1); cp_commit();
    issue(2); cp_commit();

#pragma unroll 1
    for (int kc = 0; kc < NCHUNK; ++kc) {
        cp_wait2();
        __syncthreads();
        if (kc + 3 < NCHUNK) issue(kc + 3);
        cp_commit();

        const float* __restrict__ bufW = sm + (kc & 3) * STAGE_F;
        const float* __restrict__ bufS = bufW + WSTG;
#pragma unroll
        for (int kk = 0; kk < 32; ++kk) {
            // a splats: dup W gives {m0,m0},{m1,m1},{m2,m2},{m3,m3}
            ulonglong2 A0 = *(const ulonglong2*)&bufW[kk * 128 + ty * 8];
            ulonglong2 A1 = *(const ulonglong2*)&bufW[kk * 128 + ty * 8 + 4];
            // b pairs: {b0,b1},{b2,b3}
            ulonglong2 Bp = *(const ulonglong2*)&bufS[kk * 68 + tx * 4];
            fma2(acc2[0][0], A0.x, Bp.x); fma2(acc2[0][1], A0.x, Bp.y);
            fma2(acc2[1][0], A0.y, Bp.x); fma2(acc2[1][1], A0.y, Bp.y);
            fma2(acc2[2][0], A1.x, Bp.x); fma2(acc2[2][1], A1.x, Bp.y);
            fma2(acc2[3][0], A1.y, Bp.x); fma2(acc2[3][1], A1.y, Bp.y);
        }
    }
    __syncthreads();   // all compute done before stage 0 reuse for gates

    // dump gates to shared: SG[m][n], m = quadrant*16 + jj
#pragma unroll
    for (int i = 0; i < 4; ++i) {
        int m = ty * 4 + i;
#pragma unroll
        for (int p = 0; p < 2; ++p) {
            float lo, hi;
            unpack2(acc2[i][p], lo, hi);
            sm[m * 68 + tx * 4 + 2 * p]     = lo;
            sm[m * 68 + tx * 4 + 2 * p + 1] = hi;
        }
    }
    __syncthreads();

    // elementwise LSTM cell + output projection partial
    const int n = tid & 63;
    const int b = b0 + n;
    float yp = 0.0f;
#pragma unroll
    for (int i = 0; i < 4; ++i) {
        int jj = (tid >> 6) + i * 4;  // 0..15
        int j = j0 + jj;
        float gi = sm[(jj)      * 68 + n] + g_bias[j];
        float gf = sm[(16 + jj) * 68 + n] + g_bias[HH + j];
        float gg = sm[(32 + jj) * 68 + n] + g_bias[2 * HH + j];
        float go = sm[(48 + jj) * 68 + n] + g_bias[3 * HH + j];
        float iv = fsig(gi);
        float fv = fsig(gf);
        float gv = ftanh(gg);
        float ov = fsig(go);
        float c = g_c[j * BB + b];
        float cn = fv * c + iv * gv;
        g_c[j * BB + b] = cn;
        float hn = ov * ftanh(cn);
        hout[j * BB + b] = hn;
        yp += hn * W_out[j];
    }
    __syncthreads();
    sm[tid] = yp;
    __syncthreads();
    if (tid < 64) {
        float y = sm[tid] + sm[tid + 64] + sm[tid + 128] + sm[tid + 192];
        atomicAdd(&out[(b0 + tid) * TT + t], y);
    }
}

// ---------------------------------------------------------------- launch ----
extern "C" void kernel_launch(void* const* d_in, const int* in_sizes, int n_in,
                              void* d_out, int out_size) {
    const float* obs   = (const float*)d_in[0];
    const float* act   = (const float*)d_in[1];
    const float* W_ih  = (const float*)d_in[2];
    const float* W_hh  = (const float*)d_in[3];
    const float* b_ih  = (const float*)d_in[4];
    const float* b_hh  = (const float*)d_in[5];
    const float* W_out = (const float*)d_in[6];
    const float* b_out = (const float*)d_in[7];
    const float* h0    = (const float*)d_in[8];
    const float* c0    = (const float*)d_in[9];
    float* out = (float*)d_out;

    cudaFuncSetAttribute(step_kernel,
                         cudaFuncAttributeMaxDynamicSharedMemorySize, SMEM_BYTES);

    k_bias<<<8, 256>>>(b_ih, b_hh);
    k_out_init<<<(BB * TT) / 256, 256>>>(out, b_out);
    k_wt<<<(KTOT * G4) / 256, 256>>>(W_hh, W_ih);
    k_xt<<<dim3(TT, DIN / 32, BB / 32), dim3(32, 8)>>>(obs, act);
    k_state<<<(HH * BB) / 256, 256>>>(h0, c0);

    for (int t = 0; t < TT; ++t) {
        step_kernel<<<dim3(HH / 16, BB / 64), 256, SMEM_BYTES>>>(t, t & 1, W_out, out);
    }
}

// round 15
// speedup vs baseline: 2.0362x; 2.0362x over previous
#include <cuda_runtime.h>
#include <cuda_bf16.h>
#include <stdint.h>
#include <math.h>

#define BB 256      // batch
#define TT 512      // time
#define NPOS 128
#define NACT 32
#define HH 512      // hidden
#define G4 2048     // 4*H
#define KP2 768     // padded K: 512 h + 160 x + 96 zero
#define KXP 256     // padded x K region (160 data + 96 zero)
#define NKC 6       // k chunks of 128

// smem stage: A_hi[64x272B] A_lo B_hi B_lo
#define ROWB 272                     // 256 data bytes + 16 pad (ldmatrix conflict-free)
#define MATB (64 * ROWB)             // 17408
#define STGB (4 * MATB)              // 69632
#define SMEM_BYTES (3 * STGB)        // 208896

// ---- persistent scratch (device globals) ----
__device__ __align__(16) __nv_bfloat16 g_Wh[G4 * KP2];      // row r=jt*64+m, m=(quad*16+jj)
__device__ __align__(16) __nv_bfloat16 g_Wl[G4 * KP2];
__device__ __align__(16) __nv_bfloat16 g_xh[TT * BB * KXP]; // [t][b][kx]
__device__ __align__(16) __nv_bfloat16 g_xl[TT * BB * KXP];
__device__ __align__(16) __nv_bfloat16 g_hb[2][2][BB * HH]; // [par][hi/lo][b][j]
__device__ float g_c[HH * BB];                              // c [j][b]
__device__ float g_bias[G4];

// ------------------------------------------------------------------ init ----
__global__ void k_bias(const float* __restrict__ b_ih, const float* __restrict__ b_hh) {
    int i = blockIdx.x * blockDim.x + threadIdx.x;
    if (i < G4) g_bias[i] = b_ih[i] + b_hh[i];
}

__global__ void k_out_init(float* __restrict__ out, const float* __restrict__ b_out) {
    int i = blockIdx.x * blockDim.x + threadIdx.x;
    if (i < BB * TT) out[i] = b_out[0];
}

// W split into CTA-tiled row order: r = jt*64 + (quad*16 + jj); gate g = quad*512 + jt*16 + jj
__global__ void k_wsplit(const float* __restrict__ W_hh, const float* __restrict__ W_ih) {
    int idx = blockIdx.x * blockDim.x + threadIdx.x;
    if (idx >= G4 * KP2) return;
    int r = idx / KP2;
    int k = idx - r * KP2;
    int jt = r >> 6;
    int quad = (r >> 4) & 3;
    int jj = r & 15;
    int g = quad * HH + jt * 16 + jj;
    float w = 0.0f;
    if (k < HH) w = W_hh[g * HH + k];
    else if (k < HH + 160) w = W_ih[g * 160 + (k - HH)];
    __nv_bfloat16 hi = __float2bfloat16(w);
    g_Wh[idx] = hi;
    g_Wl[idx] = __float2bfloat16(w - __bfloat162float(hi));
}

// x split: [t][b][kx], kx<128 obs, 128..159 act, 160..255 zero
__global__ void k_xsplit(const float* __restrict__ obs, const float* __restrict__ act) {
    long idx = (long)blockIdx.x * blockDim.x + threadIdx.x;
    if (idx >= (long)TT * BB * KXP) return;
    int kx = idx & (KXP - 1);
    long rest = idx >> 8;
    int b = rest % BB;
    int t = rest / BB;
    float v = 0.0f;
    if (kx < NPOS)      v = obs[((long)b * TT + t) * NPOS + kx];
    else if (kx < 160)  v = act[((long)b * TT + t) * NACT + (kx - NPOS)];
    __nv_bfloat16 hi = __float2bfloat16(v);
    g_xh[idx] = hi;
    g_xl[idx] = __float2bfloat16(v - __bfloat162float(hi));
}

__global__ void k_hsplit(const float* __restrict__ h0) {
    int idx = blockIdx.x * blockDim.x + threadIdx.x;   // = b*512 + j
    if (idx >= BB * HH) return;
    float v = h0[idx];
    __nv_bfloat16 hi = __float2bfloat16(v);
    g_hb[0][0][idx] = hi;
    g_hb[0][1][idx] = __float2bfloat16(v - __bfloat162float(hi));
}

__global__ void k_cinit(const float* __restrict__ c0) {
    int idx = blockIdx.x * blockDim.x + threadIdx.x;
    if (idx >= HH * BB) return;
    int j = idx >> 8;
    int b = idx & 255;
    g_c[idx] = c0[b * HH + j];   // g_c[j][b]
}

// ------------------------------------------------------------- utilities ----
__device__ __forceinline__ void cp16(uint32_t saddr, const void* g) {
    asm volatile("cp.async.cg.shared.global [%0], [%1], 16;"
                 :: "r"(saddr), "l"(g) : "memory");
}
__device__ __forceinline__ void cp_commit() {
    asm volatile("cp.async.commit_group;" ::: "memory");
}
__device__ __forceinline__ void cp_wait1() {
    asm volatile("cp.async.wait_group 1;" ::: "memory");
}

#define LDSM_X4(R0, R1, R2, R3, ADDR) \
    asm volatile("ldmatrix.sync.aligned.m8n8.x4.shared.b16 {%0,%1,%2,%3}, [%4];" \
                 : "=r"(R0), "=r"(R1), "=r"(R2), "=r"(R3) : "r"(ADDR))

#define MMA16816(D, A0, A1, A2, A3, B0, B1) \
    asm volatile("mma.sync.aligned.m16n8k16.row.col.f32.bf16.bf16.f32 " \
                 "{%0,%1,%2,%3}, {%4,%5,%6,%7}, {%8,%9}, {%0,%1,%2,%3};" \
                 : "+f"((D)[0]), "+f"((D)[1]), "+f"((D)[2]), "+f"((D)[3]) \
                 : "r"(A0), "r"(A1), "r"(A2), "r"(A3), "r"(B0), "r"(B1))

__device__ __forceinline__ float fsig(float x) { return 1.0f / (1.0f + __expf(-x)); }
__device__ __forceinline__ float ftanh(float x) { return 1.0f - 2.0f / (__expf(2.0f * x) + 1.0f); }

// ------------------------------------------------------------------ step ----
// grid (32 j-tiles, 4 b-tiles), 256 threads (8 warps: 2 m x 4 n).
// CTA: 64 gate rows (m = quad*16+jj) x 64 batch, K=768, 6 chunks of 128.
// bf16x3 split via mma.sync m16n8k16, fp32 accumulate in registers.
__global__ void __launch_bounds__(256, 1)
step_kernel(int t, int par, const float* __restrict__ Wout, float* __restrict__ out) {
    extern __shared__ char ds[];
    uint32_t sb;
    asm("{ .reg .u64 tt; cvta.to.shared.u64 tt, %1; cvt.u32.u64 %0, tt; }"
        : "=r"(sb) : "l"(ds));

    const int tid  = threadIdx.x;
    const int lane = tid & 31;
    const int wid  = tid >> 5;
    const int mw   = wid >> 2;       // 0/1
    const int nw   = wid & 3;        // 0..3
    const int jt   = blockIdx.x;     // 0..31
    const int j0   = jt * 16;
    const int r0   = jt * 64;
    const int b0   = blockIdx.y * 64;

    const __nv_bfloat16* __restrict__ hh = g_hb[par][0];
    const __nv_bfloat16* __restrict__ hl = g_hb[par][1];
    __nv_bfloat16* __restrict__ hoh = g_hb[par ^ 1][0];
    __nv_bfloat16* __restrict__ hol = g_hb[par ^ 1][1];

    // ---- cp.async slots: A 8/thread, B 8/thread (hi buf s<4, lo buf s>=4,
    // s and s+4 share row/col) ----
    uint32_t soA[4], soB[4];
    int goA[4], goBh[4];
    long goBx[4];
#pragma unroll
    for (int s = 0; s < 4; ++s) {
        int oo = tid + 256 * s;          // 0..1023
        int row = oo >> 4;
        int c16 = oo & 15;
        soA[s]  = (uint32_t)(row * ROWB + c16 * 16);
        soB[s]  = (uint32_t)(2 * MATB + row * ROWB + c16 * 16);
        goA[s]  = (r0 + row) * KP2 + c16 * 8;
        goBh[s] = (b0 + row) * HH + c16 * 8;
        goBx[s] = ((long)t * BB + b0 + row) * KXP + c16 * 8;
    }

    auto issue = [&](int c) {
        uint32_t stg = sb + (uint32_t)(c % 3) * STGB;
        int ka = c * 128;
#pragma unroll
        for (int s = 0; s < 4; ++s) {
            cp16(stg + soA[s],        g_Wh + goA[s] + ka);
            cp16(stg + soA[s] + MATB, g_Wl + goA[s] + ka);
        }
        if (c < 4) {
#pragma unroll
            for (int s = 0; s < 4; ++s) {
                cp16(stg + soB[s],        hh + goBh[s] + ka);
                cp16(stg + soB[s] + MATB, hl + goBh[s] + ka);
            }
        } else {
            int kb = (c - 4) * 128;
#pragma unroll
            for (int s = 0; s < 4; ++s) {
                cp16(stg + soB[s],        g_xh + goBx[s] + kb);
                cp16(stg + soB[s] + MATB, g_xl + goBx[s] + kb);
            }
        }
    };

    issue(0); cp_commit();
    issue(1); cp_commit();

    // ldmatrix per-thread byte offsets
    const uint32_t aoff = (uint32_t)((lane & 15) * ROWB + (lane >> 4) * 16);
    const uint32_t am0 = aoff + (uint32_t)(mw * 32) * ROWB;       // m-frag 0
    const uint32_t am1 = am0 + 16u * ROWB;                        // m-frag 1
    const uint32_t boff = (uint32_t)((nw * 16 + (lane & 7) + ((lane >> 4) & 1) * 8) * ROWB
                                     + ((lane >> 3) & 1) * 16);

    float accA[2][2][4];   // Ah*Bh
    float accB[2][2][4];   // Ah*Bl + Al*Bh
#pragma unroll
    for (int i = 0; i < 2; ++i)
#pragma unroll
        for (int j = 0; j < 2; ++j)
#pragma unroll
            for (int e = 0; e < 4; ++e) { accA[i][j][e] = 0.0f; accB[i][j][e] = 0.0f; }

#pragma unroll 1
    for (int c = 0; c < NKC; ++c) {
        cp_wait1();
        __syncthreads();
        if (c + 2 < NKC) issue(c + 2);
        cp_commit();

        const uint32_t stg = sb + (uint32_t)(c % 3) * STGB;
        const uint32_t Ah = stg, Al = stg + MATB;
        const uint32_t Bh = stg + 2 * MATB, Bl = stg + 3 * MATB;

#pragma unroll
        for (int ks = 0; ks < 8; ++ks) {
            const uint32_t ko = (uint32_t)ks * 32;
            uint32_t ah0[4], ah1[4], al0[4], al1[4], bh[4], bl[4];
            LDSM_X4(ah0[0], ah0[1], ah0[2], ah0[3], Ah + am0 + ko);
            LDSM_X4(ah1[0], ah1[1], ah1[2], ah1[3], Ah + am1 + ko);
            LDSM_X4(bh[0],  bh[1],  bh[2],  bh[3],  Bh + boff + ko);
            LDSM_X4(al0[0], al0[1], al0[2], al0[3], Al + am0 + ko);
            LDSM_X4(al1[0], al1[1], al1[2], al1[3], Al + am1 + ko);
            LDSM_X4(bl[0],  bl[1],  bl[2],  bl[3],  Bl + boff + ko);

            MMA16816(accA[0][0], ah0[0], ah0[1], ah0[2], ah0[3], bh[0], bh[1]);
            MMA16816(accA[0][1], ah0[0], ah0[1], ah0[2], ah0[3], bh[2], bh[3]);
            MMA16816(accA[1][0], ah1[0], ah1[1], ah1[2], ah1[3], bh[0], bh[1]);
            MMA16816(accA[1][1], ah1[0], ah1[1], ah1[2], ah1[3], bh[2], bh[3]);

            MMA16816(accB[0][0], ah0[0], ah0[1], ah0[2], ah0[3], bl[0], bl[1]);
            MMA16816(accB[0][1], ah0[0], ah0[1], ah0[2], ah0[3], bl[2], bl[3]);
            MMA16816(accB[1][0], ah1[0], ah1[1], ah1[2], ah1[3], bl[0], bl[1]);
            MMA16816(accB[1][1], ah1[0], ah1[1], ah1[2], ah1[3], bl[2], bl[3]);

            MMA16816(accB[0][0], al0[0], al0[1], al0[2], al0[3], bh[0], bh[1]);
            MMA16816(accB[0][1], al0[0], al0[1], al0[2], al0[3], bh[2], bh[3]);
            MMA16816(accB[1][0], al1[0], al1[1], al1[2], al1[3], bh[0], bh[1]);
            MMA16816(accB[1][1], al1[0], al1[1], al1[2], al1[3], bh[2], bh[3]);
        }
    }

    // ---------------- epilogue ----------------
    // reuse smem: gates sg[64 m][66] f32, then h hi/lo + y partials
    float* sg = (float*)ds;                                 // 16896 B
    __nv_bfloat16* shh = (__nv_bfloat16*)(ds + 16896);      // [64 n][16 jj]
    __nv_bfloat16* shl = shh + 64 * 16;
    float* sy = (float*)(ds + 16896 + 4096);                // 256 floats

    // write fragments (lagging warps only touch stage 2 region, disjoint)
    {
        const int r = lane >> 2;
        const int cc = (lane & 3) * 2;
#pragma unroll
        for (int mf = 0; mf < 2; ++mf) {
            int mbase = mw * 32 + mf * 16;
#pragma unroll
            for (int nf = 0; nf < 2; ++nf) {
                int nbase = nw * 16 + nf * 8 + cc;
                float2 v0 = make_float2(accA[mf][nf][0] + accB[mf][nf][0],
                                        accA[mf][nf][1] + accB[mf][nf][1]);
                float2 v1 = make_float2(accA[mf][nf][2] + accB[mf][nf][2],
                                        accA[mf][nf][3] + accB[mf][nf][3]);
                *(float2*)&sg[(mbase + r) * 66 + nbase]     = v0;
                *(float2*)&sg[(mbase + r + 8) * 66 + nbase] = v1;
            }
        }
    }
    __syncthreads();

    // LSTM cell + output projection partial
    const int n = tid & 63;
    const int b = b0 + n;
    float yp = 0.0f;
#pragma unroll
    for (int i = 0; i < 4; ++i) {
        int jj = (tid >> 6) + i * 4;    // 0..15
        int j = j0 + jj;
        float gi = sg[(jj)      * 66 + n] + g_bias[j];
        float gf = sg[(16 + jj) * 66 + n] + g_bias[HH + j];
        float gg = sg[(32 + jj) * 66 + n] + g_bias[2 * HH + j];
        float go = sg[(48 + jj) * 66 + n] + g_bias[3 * HH + j];
        float iv = fsig(gi);
        float fv = fsig(gf);
        float gv = ftanh(gg);
        float ov = fsig(go);
        float c = g_c[j * BB + b];
        float cn = fv * c + iv * gv;
        g_c[j * BB + b] = cn;
        float hn = ov * ftanh(cn);
        __nv_bfloat16 hi = __float2bfloat16(hn);
        shh[n * 16 + jj] = hi;
        shl[n * 16 + jj] = __float2bfloat16(hn - __bfloat162float(hi));
        yp += hn * Wout[j];
    }
    sy[tid] = yp;
    __syncthreads();
    if (tid < 64) {
        float y = sy[tid] + sy[tid + 64] + sy[tid + 128] + sy[tid + 192];
        atomicAdd(&out[(b0 + tid) * TT + t], y);
    }

    // h writeback: 2 terms x 64 n x 16 jj bf16 = 2 x 2048 B; 16B/op, 1 op/thread
    {
        int term = tid >> 7;
        int rest = tid & 127;
        int nn = rest >> 1, half = rest & 1;
        const uint4 v = *(const uint4*)((term ? shl : shh) + nn * 16 + half * 8);
        __nv_bfloat16* dst = (term ? hol : hoh) + (long)(b0 + nn) * HH + j0 + half * 8;
        *(uint4*)dst = v;
    }
}

// ---------------------------------------------------------------- launch ----
extern "C" void kernel_launch(void* const* d_in, const int* in_sizes, int n_in,
                              void* d_out, int out_size) {
    const float* obs   = (const float*)d_in[0];
    const float* act   = (const float*)d_in[1];
    const float* W_ih  = (const float*)d_in[2];
    const float* W_hh  = (const float*)d_in[3];
    const float* b_ih  = (const float*)d_in[4];
    const float* b_hh  = (const float*)d_in[5];
    const float* W_out = (const float*)d_in[6];
    const float* b_out = (const float*)d_in[7];
    const float* h0    = (const float*)d_in[8];
    const float* c0    = (const float*)d_in[9];
    float* out = (float*)d_out;

    cudaFuncSetAttribute(step_kernel,
                         cudaFuncAttributeMaxDynamicSharedMemorySize, SMEM_BYTES);

    k_bias<<<8, 256>>>(b_ih, b_hh);
    k_out_init<<<(BB * TT) / 256, 256>>>(out, b_out);
    k_wsplit<<<(G4 * KP2) / 256, 256>>>(W_hh, W_ih);
    {
        long nx = (long)TT * BB * KXP;
        k_xsplit<<<(unsigned)((nx + 255) / 256), 256>>>(obs, act);
    }
    k_hsplit<<<(BB * HH) / 256, 256>>>(h0);
    k_cinit<<<(HH * BB) / 256, 256>>>(c0);

    for (int t = 0; t < TT; ++t) {
        step_kernel<<<dim3(32, 4), 256, SMEM_BYTES>>>(t, t & 1, W_out, out);
    }
}

// round 16
// speedup vs baseline: 2.1037x; 1.0332x over previous
#include <cuda_runtime.h>
#include <cuda_bf16.h>
#include <stdint.h>
#include <math.h>

#define BB 256      // batch
#define TT 512      // time
#define NPOS 128
#define NACT 32
#define DIN 160
#define HH 512      // hidden
#define G4 2048     // 4*H
#define KTOT 672    // 512 h + 160 x
#define NKC 21      // chunks of 32
#define NCTA 128

// ---- smem layout (bytes) ----
// A_hi [64 rows x 1360B]  @ 0          (87,040)
// A_lo                     @ 87040      (87,040)
// B stages x3              @ 174080     (3 x 10240: Bh 5120 + Bl 5120; row 80B)
// sg gates f32 [64][66]    @ 204800     (16,896)   (sy overlays sg)
// c  f32 [16jj][64n]       @ 221696     (4,096)
// shh/shl overlay B stage0 @ 174080 / 176128
#define A_LO_OFF 87040
#define B_OFF 174080
#define B_STG 10240
#define SG_OFF 204800
#define C_OFF 221696
#define SMEM_BYTES 225792

// ---- persistent scratch (device globals) ----
__device__ __align__(16) __nv_bfloat16 g_Wh[G4 * KTOT];     // [r][k], r = jt*64+quad*16+jj
__device__ __align__(16) __nv_bfloat16 g_Wl[G4 * KTOT];
__device__ __align__(16) __nv_bfloat16 g_xh[(long)TT * BB * DIN]; // [t][b][kx]
__device__ __align__(16) __nv_bfloat16 g_xl[(long)TT * BB * DIN];
__device__ __align__(16) __nv_bfloat16 g_hb[2][2][BB * HH]; // [par][hi/lo][b][j]
__device__ float g_bias[G4];
__device__ unsigned int g_barr[TT];

// ------------------------------------------------------------------ init ----
__global__ void k_bias(const float* __restrict__ b_ih, const float* __restrict__ b_hh) {
    int i = blockIdx.x * blockDim.x + threadIdx.x;
    if (i < G4) g_bias[i] = b_ih[i] + b_hh[i];
}

__global__ void k_out_init(float* __restrict__ out, const float* __restrict__ b_out) {
    int i = blockIdx.x * blockDim.x + threadIdx.x;
    if (i < BB * TT) out[i] = b_out[0];
}

__global__ void k_barinit() {
    int i = blockIdx.x * blockDim.x + threadIdx.x;
    if (i < TT) g_barr[i] = 0u;
}

// W split: r = jt*64 + quad*16 + jj ; gate g = quad*512 + jt*16 + jj
__global__ void k_wsplit(const float* __restrict__ W_hh, const float* __restrict__ W_ih) {
    int idx = blockIdx.x * blockDim.x + threadIdx.x;
    if (idx >= G4 * KTOT) return;
    int r = idx / KTOT;
    int k = idx - r * KTOT;
    int jt = r >> 6;
    int quad = (r >> 4) & 3;
    int jj = r & 15;
    int g = quad * HH + jt * 16 + jj;
    float w = (k < HH) ? W_hh[g * HH + k] : W_ih[g * DIN + (k - HH)];
    __nv_bfloat16 hi = __float2bfloat16(w);
    g_Wh[idx] = hi;
    g_Wl[idx] = __float2bfloat16(w - __bfloat162float(hi));
}

// x split: [t][b][kx]
__global__ void k_xsplit(const float* __restrict__ obs, const float* __restrict__ act) {
    long idx = (long)blockIdx.x * blockDim.x + threadIdx.x;
    if (idx >= (long)TT * BB * DIN) return;
    int kx = (int)(idx % DIN);
    long rest = idx / DIN;
    int b = (int)(rest % BB);
    int t = (int)(rest / BB);
    float v = (kx < NPOS) ? obs[((long)b * TT + t) * NPOS + kx]
                          : act[((long)b * TT + t) * NACT + (kx - NPOS)];
    __nv_bfloat16 hi = __float2bfloat16(v);
    g_xh[idx] = hi;
    g_xl[idx] = __float2bfloat16(v - __bfloat162float(hi));
}

__global__ void k_hsplit(const float* __restrict__ h0) {
    int idx = blockIdx.x * blockDim.x + threadIdx.x;   // = b*512 + j
    if (idx >= BB * HH) return;
    float v = h0[idx];
    __nv_bfloat16 hi = __float2bfloat16(v);
    g_hb[0][0][idx] = hi;
    g_hb[0][1][idx] = __float2bfloat16(v - __bfloat162float(hi));
}

// ------------------------------------------------------------- utilities ----
__device__ __forceinline__ void cp16(uint32_t saddr, const void* g) {
    asm volatile("cp.async.cg.shared.global [%0], [%1], 16;"
                 :: "r"(saddr), "l"(g) : "memory");
}
__device__ __forceinline__ void cp_commit() {
    asm volatile("cp.async.commit_group;" ::: "memory");
}
__device__ __forceinline__ void cp_wait1() {
    asm volatile("cp.async.wait_group 1;" ::: "memory");
}
__device__ __forceinline__ void cp_wait0() {
    asm volatile("cp.async.wait_group 0;" ::: "memory");
}

#define LDSM_X4(R0, R1, R2, R3, ADDR) \
    asm volatile("ldmatrix.sync.aligned.m8n8.x4.shared.b16 {%0,%1,%2,%3}, [%4];" \
                 : "=r"(R0), "=r"(R1), "=r"(R2), "=r"(R3) : "r"(ADDR))

#define MMA16816(D, A0, A1, A2, A3, B0, B1) \
    asm volatile("mma.sync.aligned.m16n8k16.row.col.f32.bf16.bf16.f32 " \
                 "{%0,%1,%2,%3}, {%4,%5,%6,%7}, {%8,%9}, {%0,%1,%2,%3};" \
                 : "+f"((D)[0]), "+f"((D)[1]), "+f"((D)[2]), "+f"((D)[3]) \
                 : "r"(A0), "r"(A1), "r"(A2), "r"(A3), "r"(B0), "r"(B1))

__device__ __forceinline__ float fsig(float x) { return 1.0f / (1.0f + __expf(-x)); }
__device__ __forceinline__ float ftanh(float x) { return 1.0f - 2.0f / (__expf(2.0f * x) + 1.0f); }

// ------------------------------------------------------------- persistent ----
// grid (32 j-tiles, 4 b-tiles) = 128 CTAs, 256 threads (8 warps, 2m x 4n).
// W tile resident in smem for all 512 steps; c resident in smem;
// per-step: B (h/x) via 3-stage cp.async, bf16x3 mma.sync, LSTM cell epilogue,
// h bf16 hi/lo global ping-pong, grid-wide barrier per step.
__global__ void __launch_bounds__(256, 1)
lstm_persist(const float* __restrict__ Wout, float* __restrict__ out,
             const float* __restrict__ c0) {
    extern __shared__ char ds[];
    uint32_t sb;
    asm("{ .reg .u64 tt; cvta.to.shared.u64 tt, %1; cvt.u32.u64 %0, tt; }"
        : "=r"(sb) : "l"(ds));

    const int tid  = threadIdx.x;
    const int lane = tid & 31;
    const int wid  = tid >> 5;
    const int mw   = wid >> 2;       // 0/1
    const int nw   = wid & 3;        // 0..3
    const int jt   = blockIdx.x;     // 0..31
    const int j0   = jt * 16;
    const int r0   = jt * 64;
    const int b0   = blockIdx.y * 64;

    float* sg   = (float*)(ds + SG_OFF);
    float* c_sm = (float*)(ds + C_OFF);
    __nv_bfloat16* shh = (__nv_bfloat16*)(ds + B_OFF);          // overlay stage0
    __nv_bfloat16* shl = (__nv_bfloat16*)(ds + B_OFF + 2048);
    float* sy = sg;                                             // overlay

    // ---- load W tile into smem (once) ----
#pragma unroll 1
    for (int s = 0; s < 42; ++s) {
        int idx = tid + 256 * s;          // 0..10751
        int mat = idx / 5376;
        int rem = idx - mat * 5376;
        int row = rem / 84;
        int c16 = rem - row * 84;
        uint32_t so = (uint32_t)(mat * A_LO_OFF + row * 1360 + c16 * 16);
        const __nv_bfloat16* src = (mat ? g_Wl : g_Wh) + (r0 + row) * KTOT + c16 * 8;
        cp16(sb + so, src);
    }
    cp_commit();

    // ---- load c tile into smem: c_sm[jj*64+n] = c0[(b0+n)*HH + j0+jj] ----
#pragma unroll
    for (int s = 0; s < 4; ++s) {
        int idx = tid + 256 * s;          // 0..1023
        int jj = idx >> 6, n = idx & 63;
        c_sm[idx] = c0[(b0 + n) * HH + j0 + jj];
    }
    cp_wait0();
    __syncthreads();

    // ---- fragment address maps ----
    const uint32_t aoff = (uint32_t)((lane & 15) * 1360 + (lane >> 4) * 16);
    const uint32_t am0 = aoff + (uint32_t)(mw * 32) * 1360;
    const uint32_t am1 = am0 + 16u * 1360;
    const uint32_t boff = (uint32_t)((nw * 16 + (lane & 7) + ((lane >> 4) & 1) * 8) * 80
                                     + ((lane >> 3) & 1) * 16);

    // ---- B cp.async slot (1 per thread per matrix) ----
    const int brow = tid >> 2;            // 0..63
    const int bc16 = tid & 3;             // 0..3
    const uint32_t soB = (uint32_t)(brow * 80 + bc16 * 16);
    const int hbase = (b0 + brow) * HH + bc16 * 8;
    const long xbase = (long)(b0 + brow) * DIN + bc16 * 8;

#pragma unroll 1
    for (int t = 0; t < TT; ++t) {
        const int par = t & 1;
        const __nv_bfloat16* __restrict__ hh = g_hb[par][0];
        const __nv_bfloat16* __restrict__ hl = g_hb[par][1];
        __nv_bfloat16* __restrict__ hoh = g_hb[par ^ 1][0];
        __nv_bfloat16* __restrict__ hol = g_hb[par ^ 1][1];
        const long xtb = (long)t * BB * DIN;

        auto issueB = [&](int c) {
            uint32_t sB = sb + B_OFF + (uint32_t)(c % 3) * B_STG;
            if (c < 16) {
                int k0 = c * 32;
                cp16(sB + soB,        hh + hbase + k0);
                cp16(sB + soB + 5120, hl + hbase + k0);
            } else {
                long xo = xtb + xbase + (c - 16) * 32;
                cp16(sB + soB,        g_xh + xo);
                cp16(sB + soB + 5120, g_xl + xo);
            }
        };

        float accA[2][2][4], accB[2][2][4];
#pragma unroll
        for (int i = 0; i < 2; ++i)
#pragma unroll
            for (int j = 0; j < 2; ++j)
#pragma unroll
                for (int e = 0; e < 4; ++e) { accA[i][j][e] = 0.0f; accB[i][j][e] = 0.0f; }

        issueB(0); cp_commit();
        issueB(1); cp_commit();

#pragma unroll 1
        for (int c = 0; c < NKC; ++c) {
            cp_wait1();
            __syncthreads();
            if (c + 2 < NKC) issueB(c + 2);
            cp_commit();

            const uint32_t Bh = sb + B_OFF + (uint32_t)(c % 3) * B_STG;
            const uint32_t Bl = Bh + 5120;
            const uint32_t Ah = sb;
            const uint32_t Al = sb + A_LO_OFF;

#pragma unroll
            for (int ks = 0; ks < 2; ++ks) {
                const uint32_t koA = (uint32_t)c * 64 + ks * 32;
                const uint32_t koB = (uint32_t)ks * 32;
                uint32_t ah0[4], ah1[4], al0[4], al1[4], bh[4], bl[4];
                LDSM_X4(ah0[0], ah0[1], ah0[2], ah0[3], Ah + am0 + koA);
                LDSM_X4(ah1[0], ah1[1], ah1[2], ah1[3], Ah + am1 + koA);
                LDSM_X4(bh[0],  bh[1],  bh[2],  bh[3],  Bh + boff + koB);
                LDSM_X4(al0[0], al0[1], al0[2], al0[3], Al + am0 + koA);
                LDSM_X4(al1[0], al1[1], al1[2], al1[3], Al + am1 + koA);
                LDSM_X4(bl[0],  bl[1],  bl[2],  bl[3],  Bl + boff + koB);

                MMA16816(accA[0][0], ah0[0], ah0[1], ah0[2], ah0[3], bh[0], bh[1]);
                MMA16816(accA[0][1], ah0[0], ah0[1], ah0[2], ah0[3], bh[2], bh[3]);
                MMA16816(accA[1][0], ah1[0], ah1[1], ah1[2], ah1[3], bh[0], bh[1]);
                MMA16816(accA[1][1], ah1[0], ah1[1], ah1[2], ah1[3], bh[2], bh[3]);

                MMA16816(accB[0][0], ah0[0], ah0[1], ah0[2], ah0[3], bl[0], bl[1]);
                MMA16816(accB[0][1], ah0[0], ah0[1], ah0[2], ah0[3], bl[2], bl[3]);
                MMA16816(accB[1][0], ah1[0], ah1[1], ah1[2], ah1[3], bl[0], bl[1]);
                MMA16816(accB[1][1], ah1[0], ah1[1], ah1[2], ah1[3], bl[2], bl[3]);

                MMA16816(accB[0][0], al0[0], al0[1], al0[2], al0[3], bh[0], bh[1]);
                MMA16816(accB[0][1], al0[0], al0[1], al0[2], al0[3], bh[2], bh[3]);
                MMA16816(accB[1][0], al1[0], al1[1], al1[2], al1[3], bh[0], bh[1]);
                MMA16816(accB[1][1], al1[0], al1[1], al1[2], al1[3], bh[2], bh[3]);
            }
        }

        // ---- fragments -> sg ----
        {
            const int r = lane >> 2;
            const int cc = (lane & 3) * 2;
#pragma unroll
            for (int mf = 0; mf < 2; ++mf) {
                int mbase = mw * 32 + mf * 16;
#pragma unroll
                for (int nf = 0; nf < 2; ++nf) {
                    int nbase = nw * 16 + nf * 8 + cc;
                    float2 v0 = make_float2(accA[mf][nf][0] + accB[mf][nf][0],
                                            accA[mf][nf][1] + accB[mf][nf][1]);
                    float2 v1 = make_float2(accA[mf][nf][2] + accB[mf][nf][2],
                                            accA[mf][nf][3] + accB[mf][nf][3]);
                    *(float2*)&sg[(mbase + r) * 66 + nbase]     = v0;
                    *(float2*)&sg[(mbase + r + 8) * 66 + nbase] = v1;
                }
            }
        }
        __syncthreads();

        // ---- LSTM cell (c in smem) + y partial + h split to smem ----
        const int n = tid & 63;
        float yp = 0.0f;
#pragma unroll
        for (int i = 0; i < 4; ++i) {
            int jj = (tid >> 6) + i * 4;    // 0..15
            int j = j0 + jj;
            float gi = sg[(jj)      * 66 + n] + g_bias[j];
            float gf = sg[(16 + jj) * 66 + n] + g_bias[HH + j];
            float gg = sg[(32 + jj) * 66 + n] + g_bias[2 * HH + j];
            float go = sg[(48 + jj) * 66 + n] + g_bias[3 * HH + j];
            float iv = fsig(gi);
            float fv = fsig(gf);
            float gv = ftanh(gg);
            float ov = fsig(go);
            float cc = c_sm[jj * 64 + n];
            float cn = fv * cc + iv * gv;
            c_sm[jj * 64 + n] = cn;
            float hn = ov * ftanh(cn);
            __nv_bfloat16 hi = __float2bfloat16(hn);
            shh[n * 16 + jj] = hi;
            shl[n * 16 + jj] = __float2bfloat16(hn - __bfloat162float(hi));
            yp += hn * Wout[j];
        }
        __syncthreads();     // all gate reads done -> sy may overlay sg
        sy[tid] = yp;
        __syncthreads();
        if (tid < 64) {
            float y = sy[tid] + sy[tid + 64] + sy[tid + 128] + sy[tid + 192];
            atomicAdd(&out[(b0 + tid) * TT + t], y);
        }

        // ---- h writeback (coalesced 16B) ----
        {
            int term = tid >> 7;
            int rest = tid & 127;
            int nn = rest >> 1, half = rest & 1;
            const uint4 v = *(const uint4*)((term ? shl : shh) + nn * 16 + half * 8);
            __nv_bfloat16* dst = (term ? hol : hoh) + (b0 + nn) * HH + j0 + half * 8;
            *(uint4*)dst = v;
        }

        // ---- grid barrier ----
        __threadfence();
        __syncthreads();
        if (tid == 0) {
            atomicAdd(&g_barr[t], 1u);
            while (((volatile unsigned int*)g_barr)[t] < (unsigned)NCTA) { }
        }
        __syncthreads();
    }
}

// ---------------------------------------------------------------- launch ----
extern "C" void kernel_launch(void* const* d_in, const int* in_sizes, int n_in,
                              void* d_out, int out_size) {
    const float* obs   = (const float*)d_in[0];
    const float* act   = (const float*)d_in[1];
    const float* W_ih  = (const float*)d_in[2];
    const float* W_hh  = (const float*)d_in[3];
    const float* b_ih  = (const float*)d_in[4];
    const float* b_hh  = (const float*)d_in[5];
    const float* W_out = (const float*)d_in[6];
    const float* b_out = (const float*)d_in[7];
    const float* h0    = (const float*)d_in[8];
    const float* c0    = (const float*)d_in[9];
    float* out = (float*)d_out;

    cudaFuncSetAttribute(lstm_persist,
                         cudaFuncAttributeMaxDynamicSharedMemorySize, SMEM_BYTES);

    k_bias<<<8, 256>>>(b_ih, b_hh);
    k_out_init<<<(BB * TT) / 256, 256>>>(out, b_out);
    k_barinit<<<2, 256>>>();
    k_wsplit<<<(G4 * KTOT) / 256, 256>>>(W_hh, W_ih);
    {
        long nx = (long)TT * BB * DIN;
        k_xsplit<<<(unsigned)((nx + 255) / 256), 256>>>(obs, act);
    }
    k_hsplit<<<(BB * HH) / 256, 256>>>(h0);

    lstm_persist<<<dim3(32, 4), 256, SMEM_BYTES>>>(W_out, out, c0);
}